// round 5
// baseline (speedup 1.0000x reference)
#include <cuda_runtime.h>
#include <math_constants.h>

// Problem constants
#define BQ    2
#define NQ    8192
#define KNN   16
#define WPB   8                        // warps (queries) per block
#define BLOCK 256
#define TILE  1920                     // candidates per smem tile (30 KB), multiple of 128
#define BLOCKS_PER_BATCH (NQ / WPB)    // 1024
#define NBLK  (BQ * BLOCKS_PER_BATCH)  // 2048
#define FULL  0xffffffffu
#define TOTAL_EDGES ((double)(BQ) * (double)(NQ) * (double)(KNN))

// Deterministic per-block partial sums (no atomics -> same result every replay)
__device__ float g_partials[NBLK];

__global__ __launch_bounds__(BLOCK, 6)
void knn_loss_kernel(const float* __restrict__ points_ref,
                     const float* __restrict__ points)
{
    __shared__ float4 tile[TILE];      // (x, y, z, x^2+y^2+z^2)
    __shared__ float  wsum[WPB];

    const int tid  = threadIdx.x;
    const int wid  = tid >> 5;
    const int lane = tid & 31;
    const int b    = blockIdx.x / BLOCKS_PER_BATCH;
    const int qn   = (blockIdx.x % BLOCKS_PER_BATCH) * WPB + wid;  // this warp's query

    const float* __restrict__ pr = points_ref + (size_t)b * NQ * 3;
    const float* __restrict__ pp = points     + (size_t)b * NQ * 3;

    // Query point (ref cloud) + squared norm (same expansion as reference)
    const float qx  = pr[qn * 3 + 0];
    const float qy  = pr[qn * 3 + 1];
    const float qz  = pr[qn * 3 + 2];
    const float sqn = qx * qx + qy * qy + qz * qz;

    // ================= Phase A: per-lane minima (no votes/shuffles) ==========
    float m0 = CUDART_INF_F, m1 = CUDART_INF_F, m2 = CUDART_INF_F, m3 = CUDART_INF_F;

    for (int t0 = 0; t0 < NQ; t0 += TILE) {
        const int cnt = min(TILE, NQ - t0);
        __syncthreads();
        for (int i = tid; i < cnt; i += BLOCK) {
            int   m = t0 + i;
            float x = pr[m * 3 + 0];
            float y = pr[m * 3 + 1];
            float z = pr[m * 3 + 2];
            tile[i] = make_float4(x, y, z, x * x + y * y + z * z);
        }
        __syncthreads();

        for (int s = 0; s < cnt; s += 128) {
            const float4 c0 = tile[s + lane];
            const float4 c1 = tile[s + 32 + lane];
            const float4 c2 = tile[s + 64 + lane];
            const float4 c3 = tile[s + 96 + lane];
            float d0 = fmaf(-2.0f, fmaf(qx, c0.x, fmaf(qy, c0.y, qz * c0.z)), sqn + c0.w);
            float d1 = fmaf(-2.0f, fmaf(qx, c1.x, fmaf(qy, c1.y, qz * c1.z)), sqn + c1.w);
            float d2 = fmaf(-2.0f, fmaf(qx, c2.x, fmaf(qy, c2.y, qz * c2.z)), sqn + c2.w);
            float d3 = fmaf(-2.0f, fmaf(qx, c3.x, fmaf(qy, c3.y, qz * c3.z)), sqn + c3.w);
            // Exclude self (warp-uniform rare branch)
            const unsigned rel = (unsigned)(qn - (t0 + s));
            if (rel < 128u) {
                if (lane == (int)(rel & 31u)) {
                    switch (rel >> 5) {
                        case 0: d0 = CUDART_INF_F; break;
                        case 1: d1 = CUDART_INF_F; break;
                        case 2: d2 = CUDART_INF_F; break;
                        default: d3 = CUDART_INF_F; break;
                    }
                }
            }
            m0 = fminf(m0, d0); m1 = fminf(m1, d1);
            m2 = fminf(m2, d2); m3 = fminf(m3, d3);
        }
    }

    // T = 16th-smallest of the 32 per-lane minima: a valid upper bound on the
    // true 16th-NN distance (16 lanes with smallest minima give 16 distinct
    // candidates <= T). Bitonic sort across the warp, then broadcast lane 15.
    float val = fminf(fminf(m0, m1), fminf(m2, m3));
#pragma unroll
    for (int k = 2; k <= 32; k <<= 1) {
#pragma unroll
        for (int j = k >> 1; j >= 1; j >>= 1) {
            float other = __shfl_xor_sync(FULL, val, j);
            bool up = ((lane & k) == 0);
            bool takeMin = (up == ((lane & j) == 0));
            val = takeMin ? fminf(val, other) : fmaxf(val, other);
        }
    }
    const float T  = __shfl_sync(FULL, val, KNN - 1);
    const float TB = T + fmaxf(fabsf(T) * 1e-5f, 1e-10f);   // robustness slack

    // ================= Phase B: collect all d2 <= TB, keep stable top-16 =====
    // Lane l (l<16) holds the (l+1)-th smallest; insertion is stable on ties
    // by ascending candidate index (matches top_k), so the final 16-set is
    // exactly the reference's.
    float kd = CUDART_INF_F;
    int   ki = -1;

    for (int t0 = 0; t0 < NQ; t0 += TILE) {
        const int cnt = min(TILE, NQ - t0);
        __syncthreads();
        for (int i = tid; i < cnt; i += BLOCK) {
            int   m = t0 + i;
            float x = pr[m * 3 + 0];
            float y = pr[m * 3 + 1];
            float z = pr[m * 3 + 2];
            tile[i] = make_float4(x, y, z, x * x + y * y + z * z);
        }
        __syncthreads();

        for (int s = 0; s < cnt; s += 128) {
            const float4 c0 = tile[s + lane];
            const float4 c1 = tile[s + 32 + lane];
            const float4 c2 = tile[s + 64 + lane];
            const float4 c3 = tile[s + 96 + lane];
            float d0 = fmaf(-2.0f, fmaf(qx, c0.x, fmaf(qy, c0.y, qz * c0.z)), sqn + c0.w);
            float d1 = fmaf(-2.0f, fmaf(qx, c1.x, fmaf(qy, c1.y, qz * c1.z)), sqn + c1.w);
            float d2 = fmaf(-2.0f, fmaf(qx, c2.x, fmaf(qy, c2.y, qz * c2.z)), sqn + c2.w);
            float d3 = fmaf(-2.0f, fmaf(qx, c3.x, fmaf(qy, c3.y, qz * c3.z)), sqn + c3.w);
            const int sg = t0 + s;
            const unsigned rel = (unsigned)(qn - sg);
            if (rel < 128u) {
                if (lane == (int)(rel & 31u)) {
                    switch (rel >> 5) {
                        case 0: d0 = CUDART_INF_F; break;
                        case 1: d1 = CUDART_INF_F; break;
                        case 2: d2 = CUDART_INF_F; break;
                        default: d3 = CUDART_INF_F; break;
                    }
                }
            }
            const float mn = fminf(fminf(d0, d1), fminf(d2, d3));
            if (__ballot_sync(FULL, mn <= TB)) {
#pragma unroll
                for (int u = 0; u < 4; ++u) {
                    const float du = (u == 0) ? d0 : (u == 1) ? d1 : (u == 2) ? d2 : d3;
                    unsigned mu = __ballot_sync(FULL, du <= TB);
                    while (mu) {
                        const int   src = __ffs(mu) - 1;
                        const float v   = __shfl_sync(FULL, du, src);
                        const int   vi  = sg + u * 32 + src;    // index affine in lane
                        // stable insertion; pos==16 is naturally a no-op
                        const unsigned le  = __ballot_sync(FULL, (lane < KNN) && (kd <= v));
                        const int      pos = __popc(le);
                        const float kdu = __shfl_up_sync(FULL, kd, 1);
                        const int   kiu = __shfl_up_sync(FULL, ki, 1);
                        if (lane >= pos) {
                            kd = (lane == pos) ? v  : kdu;
                            ki = (lane == pos) ? vi : kiu;
                        }
                        mu &= mu - 1;
                    }
                }
            }
        }
    }

    // ---- Edge lengths + L1: lanes 0..15 each handle one neighbor ----
    const float pqx = pp[qn * 3 + 0];
    const float pqy = pp[qn * 3 + 1];
    const float pqz = pp[qn * 3 + 2];

    float partial = 0.0f;
    if (lane < KNN) {
        const int nb = ki;
        float rx = pr[nb * 3 + 0] - qx;
        float ry = pr[nb * 3 + 1] - qy;
        float rz = pr[nb * 3 + 2] - qz;
        float dref = sqrtf(rx * rx + ry * ry + rz * rz);
        float px = pp[nb * 3 + 0] - pqx;
        float py = pp[nb * 3 + 1] - pqy;
        float pz = pp[nb * 3 + 2] - pqz;
        float dprd = sqrtf(px * px + py * py + pz * pz);
        partial = fabsf(dref - dprd);
    }

    // Deterministic warp + block reduction
#pragma unroll
    for (int o = 16; o > 0; o >>= 1)
        partial += __shfl_xor_sync(FULL, partial, o);
    if (lane == 0) wsum[wid] = partial;
    __syncthreads();

    if (wid == 0) {
        float s = (lane < WPB) ? wsum[lane] : 0.0f;
#pragma unroll
        for (int o = 16; o > 0; o >>= 1)
            s += __shfl_xor_sync(FULL, s, o);
        if (lane == 0) g_partials[blockIdx.x] = s;
    }
}

__global__ void finalize_kernel(float* __restrict__ out)
{
    __shared__ double sred[256];
    int t = threadIdx.x;
    double s = 0.0;
    for (int i = t; i < NBLK; i += 256) s += (double)g_partials[i];
    sred[t] = s;
    __syncthreads();
#pragma unroll
    for (int st = 128; st > 0; st >>= 1) {
        if (t < st) sred[t] += sred[t + st];
        __syncthreads();
    }
    if (t == 0) out[0] = (float)(sred[0] / TOTAL_EDGES);
}

extern "C" void kernel_launch(void* const* d_in, const int* in_sizes, int n_in,
                              void* d_out, int out_size)
{
    (void)in_sizes; (void)n_in; (void)out_size;
    const float* points_ref = (const float*)d_in[0];
    const float* points     = (const float*)d_in[1];
    knn_loss_kernel<<<NBLK, BLOCK>>>(points_ref, points);
    finalize_kernel<<<1, 256>>>((float*)d_out);
}